// round 13
// baseline (speedup 1.0000x reference)
#include <cuda_runtime.h>
#include <cuda_fp16.h>
#include <cstdint>

// ---------------------------------------------------------------------------
// Problem constants
// ---------------------------------------------------------------------------
static constexpr int B   = 8;
static constexpr int S   = 1024;
static constexpr int D   = 1024;
static constexpr int H   = 16;
static constexpr int DH  = 64;
static constexpr int R   = 128;   // RANK
static constexpr int KC  = 16;
static constexpr int KE  = 8;

// ---------------------------------------------------------------------------
// Scratch layout (all fp16 hi/lo pairs now; no fp32 intermediates)
// ---------------------------------------------------------------------------
static constexpr size_t N_WC  = (size_t)B * D * R;
static constexpr size_t N_H   = (size_t)B * S * R;
static constexpr size_t N_WX  = (size_t)B * R * D;
static constexpr size_t N_QKV = (size_t)B * S * D;
static constexpr size_t N_WO  = (size_t)D * D;
static constexpr size_t HALVES =
    10 * N_QKV + 2 * N_WC + 6 * N_WX + 2 * N_H + 2 * N_WO;
static constexpr size_t SCRATCH_FLOATS = (HALVES + 1) / 2;

__device__ __align__(1024) float g_scratch[SCRATCH_FLOATS];

// ---------------------------------------------------------------------------
// Helpers
// ---------------------------------------------------------------------------
__device__ __forceinline__ void split2(float a, float b, uint32_t& hi, uint32_t& lo) {
    __half2 h = __floats2half2_rn(a, b);
    hi = *reinterpret_cast<uint32_t*>(&h);
    float2 f = __half22float2(h);
    __half2 l = __floats2half2_rn(a - f.x, b - f.y);
    lo = *reinterpret_cast<uint32_t*>(&l);
}

#define MMA_F16(ACC, A0, A1, A2, A3, B0, B1)                                   \
    asm volatile("mma.sync.aligned.m16n8k16.row.col.f32.f16.f16.f32 "          \
        "{%0,%1,%2,%3}, {%4,%5,%6,%7}, {%8,%9}, {%0,%1,%2,%3};"                \
        : "+f"((ACC)[0]), "+f"((ACC)[1]), "+f"((ACC)[2]), "+f"((ACC)[3])       \
        : "r"(A0), "r"(A1), "r"(A2), "r"(A3), "r"(B0), "r"(B1))

#define CP16(dst_half_ptr, src_ptr)                                            \
    asm volatile("cp.async.cg.shared.global [%0], [%1], 16;"                   \
        :: "r"((uint32_t)__cvta_generic_to_shared(dst_half_ptr)), "l"(src_ptr))

// ---------------------------------------------------------------------------
// Fused: compress combine -> transpose -> fp16 hi/lo split.
// Out: WcT[b][r][d] hi/lo (K-major for hgemm B-operand).
// grid (D/32, B), 256 threads. Each block: 32-d tile x all 128 r.
// ---------------------------------------------------------------------------
__global__ void combine_compress_T(const float* __restrict__ w,
                                   const int*   __restrict__ idx,
                                   const float* __restrict__ cn,
                                   __half* __restrict__ ohi,
                                   __half* __restrict__ olo)
{
    int dt = blockIdx.x * 32;
    int b  = blockIdx.y;
    __shared__ float s[32][129];
    __shared__ float sw[KC];
    __shared__ int   si[KC];
    int tid = threadIdx.x;
    if (tid < KC) { sw[tid] = w[b * KC + tid]; si[tid] = idx[b * KC + tid]; }
    __syncthreads();

    float a[16];
#pragma unroll
    for (int j = 0; j < 16; j++) a[j] = 0.f;
#pragma unroll
    for (int k = 0; k < KC; k++) {
        const float* src = cn + ((long)si[k] * D + dt) * R;   // contiguous 32*128
        float wk = sw[k];
#pragma unroll
        for (int j = 0; j < 16; j++)
            a[j] += wk * src[tid + j * 256];
    }
#pragma unroll
    for (int j = 0; j < 16; j++) {
        int i = tid + j * 256;            // d = i>>7, r = i&127
        s[i >> 7][i & 127] = a[j];
    }
    __syncthreads();

    int r = tid >> 1, dp = (tid & 1) * 16;
    uint32_t hb[8], lb[8];
#pragma unroll
    for (int p = 0; p < 8; p++)
        split2(s[dp + 2 * p][r], s[dp + 2 * p + 1][r], hb[p], lb[p]);
    long o = ((long)b * R + r) * D + dt + dp;
    ((uint4*)&ohi[o])[0] = ((uint4*)hb)[0];
    ((uint4*)&ohi[o])[1] = ((uint4*)hb)[1];
    ((uint4*)&olo[o])[0] = ((uint4*)lb)[0];
    ((uint4*)&olo[o])[1] = ((uint4*)lb)[1];
}

// ---------------------------------------------------------------------------
// Fused: expand combine -> transpose -> fp16 hi/lo split.
// Out: WxT[(mat*B+b)][d][r] hi/lo. grid (D/32, B, 3), 256 threads.
// ---------------------------------------------------------------------------
__global__ void combine_expand_T(const float* __restrict__ wq, const int* __restrict__ iq,
                                 const float* __restrict__ wk, const int* __restrict__ ik,
                                 const float* __restrict__ wv, const int* __restrict__ iv,
                                 const float* __restrict__ pool,
                                 __half* __restrict__ Whi, __half* __restrict__ Wlo)
{
    int dt  = blockIdx.x * 32;
    int b   = blockIdx.y;
    int mat = blockIdx.z;
    const float* w  = (mat == 0) ? wq : (mat == 1) ? wk : wv;
    const int*   id = (mat == 0) ? iq : (mat == 1) ? ik : iv;

    __shared__ float s[32][129];          // s[dd][r]
    __shared__ float sw[KE];
    __shared__ int   si[KE];
    int tid = threadIdx.x;
    if (tid < KE) { sw[tid] = w[b * KE + tid]; si[tid] = id[b * KE + tid]; }
    __syncthreads();

    float a[16];
#pragma unroll
    for (int j = 0; j < 16; j++) a[j] = 0.f;
#pragma unroll
    for (int k = 0; k < KE; k++) {
        const float* src = pool + (long)si[k] * R * D + dt;   // elem (r,dd): src[r*D+dd]
        float wk_ = sw[k];
#pragma unroll
        for (int j = 0; j < 16; j++) {
            int i = tid + j * 256;        // r = i>>5, dd = i&31
            a[j] += wk_ * src[(long)(i >> 5) * D + (i & 31)];
        }
    }
#pragma unroll
    for (int j = 0; j < 16; j++) {
        int i = tid + j * 256;
        s[i & 31][i >> 5] = a[j];
    }
    __syncthreads();

    int d = tid >> 3, rp = (tid & 7) * 16;
    uint32_t hb[8], lb[8];
#pragma unroll
    for (int p = 0; p < 8; p++)
        split2(s[d][rp + 2 * p], s[d][rp + 2 * p + 1], hb[p], lb[p]);
    long o = ((long)(mat * B + b) * D + dt + d) * R + rp;
    ((uint4*)&Whi[o])[0] = ((uint4*)hb)[0];
    ((uint4*)&Whi[o])[1] = ((uint4*)hb)[1];
    ((uint4*)&Wlo[o])[0] = ((uint4*)lb)[0];
    ((uint4*)&Wlo[o])[1] = ((uint4*)lb)[1];
}

// ---------------------------------------------------------------------------
// fp32 -> fp16 hi/lo elementwise
// ---------------------------------------------------------------------------
__global__ void split_kernel(const float* __restrict__ in,
                             __half* __restrict__ hi, __half* __restrict__ lo)
{
    long i = ((long)blockIdx.x * 256 + threadIdx.x) * 4;
    float4 v = *(const float4*)&in[i];
    uint32_t h0, l0, h1, l1;
    split2(v.x, v.y, h0, l0);
    split2(v.z, v.w, h1, l1);
    *(uint2*)&hi[i] = make_uint2(h0, h1);
    *(uint2*)&lo[i] = make_uint2(l0, l1);
}

// ---------------------------------------------------------------------------
// fp16-pair tensor-core GEMM (NPROD=3: hh+hl+lh; NPROD=2: hh+lh).
// C[M,N] = A[M,K] @ B[N,K]^T. BM=BN=128, BK=32, 256 threads.
// ---------------------------------------------------------------------------
static constexpr int TILE_H    = 128 * 40;
static constexpr int GEMM_SMEM = 2 * 4 * TILE_H * 2;  // 81920 B

template <int NPROD, bool SPLIT_OUT>
__global__ void __launch_bounds__(256)
hgemm(const __half* __restrict__ Ahi, const __half* __restrict__ Alo,
      const __half* __restrict__ Bhi, const __half* __restrict__ Blo,
      float* __restrict__ C, __half* __restrict__ Chi, __half* __restrict__ Clo,
      int K, int lda, int ldb, int ldc, long sA, long sB, long sC)
{
    extern __shared__ __half sm[];
    int tid = threadIdx.x, wid = tid >> 5, lane = tid & 31;
    int wm = wid & 1, wn = wid >> 1;
    int qr = lane >> 2, qc = lane & 3;

    long zA = (long)blockIdx.z * sA, zB = (long)blockIdx.z * sB, zC = (long)blockIdx.z * sC;
    int m0 = blockIdx.y * 128, n0 = blockIdx.x * 128;

    const __half* srcs[4] = { Ahi + zA, Alo + zA, Bhi + zB, Blo + zB };
    int rbase[4] = { m0, m0, n0, n0 };
    int lds[4]   = { lda, lda, ldb, ldb };

    float acc[4][4][4];
#pragma unroll
    for (int mi = 0; mi < 4; mi++)
#pragma unroll
        for (int ni = 0; ni < 4; ni++)
#pragma unroll
            for (int c = 0; c < 4; c++) acc[mi][ni][c] = 0.f;

    int nt = K / 32;
    constexpr int NLOAD = (NPROD == 3) ? 8 : 6;

    auto load_stage = [&](int kt, int st) {
        __half* sb = sm + st * 4 * TILE_H;
#pragma unroll
        for (int i = 0; i < NLOAD; i++) {
            int g = tid + i * 256;
            int tsr = g >> 9;
            int rem = g & 511;
            int row = rem >> 2, ch = rem & 3;
            __half* dst = sb + tsr * TILE_H + row * 40 + ch * 8;
            const __half* src = srcs[tsr] + (long)(rbase[tsr] + row) * lds[tsr]
                                + kt * 32 + ch * 8;
            CP16(dst, src);
        }
        asm volatile("cp.async.commit_group;" ::: "memory");
    };

    load_stage(0, 0);

    for (int kt = 0; kt < nt; kt++) {
        if (kt + 1 < nt) {
            load_stage(kt + 1, (kt + 1) & 1);
            asm volatile("cp.async.wait_group 1;" ::: "memory");
        } else {
            asm volatile("cp.async.wait_group 0;" ::: "memory");
        }
        __syncthreads();

        const __half* sb = sm + (kt & 1) * 4 * TILE_H;
        const __half* As_hi = sb;
        const __half* As_lo = sb + TILE_H;
        const __half* Bs_hi = sb + 2 * TILE_H;
        const __half* Bs_lo = sb + 3 * TILE_H;

#pragma unroll
        for (int ks = 0; ks < 2; ks++) {
            uint32_t ahi[4][4], alo[4][4];
#pragma unroll
            for (int mi = 0; mi < 4; mi++) {
                int base = (wm * 64 + mi * 16 + qr) * 40 + ks * 16 + qc * 2;
                ahi[mi][0] = *(const uint32_t*)&As_hi[base];
                ahi[mi][1] = *(const uint32_t*)&As_hi[base + 8 * 40];
                ahi[mi][2] = *(const uint32_t*)&As_hi[base + 8];
                ahi[mi][3] = *(const uint32_t*)&As_hi[base + 8 * 40 + 8];
                alo[mi][0] = *(const uint32_t*)&As_lo[base];
                alo[mi][1] = *(const uint32_t*)&As_lo[base + 8 * 40];
                alo[mi][2] = *(const uint32_t*)&As_lo[base + 8];
                alo[mi][3] = *(const uint32_t*)&As_lo[base + 8 * 40 + 8];
            }
            uint32_t bhi[4][2], blo[4][2];
#pragma unroll
            for (int ni = 0; ni < 4; ni++) {
                int base = (wn * 32 + ni * 8 + qr) * 40 + ks * 16 + qc * 2;
                bhi[ni][0] = *(const uint32_t*)&Bs_hi[base];
                bhi[ni][1] = *(const uint32_t*)&Bs_hi[base + 8];
                if (NPROD == 3) {
                    blo[ni][0] = *(const uint32_t*)&Bs_lo[base];
                    blo[ni][1] = *(const uint32_t*)&Bs_lo[base + 8];
                }
            }
#pragma unroll
            for (int mi = 0; mi < 4; mi++)
#pragma unroll
                for (int ni = 0; ni < 4; ni++) {
                    MMA_F16(acc[mi][ni], alo[mi][0], alo[mi][1], alo[mi][2], alo[mi][3],
                            bhi[ni][0], bhi[ni][1]);
                    if (NPROD == 3)
                        MMA_F16(acc[mi][ni], ahi[mi][0], ahi[mi][1], ahi[mi][2], ahi[mi][3],
                                blo[ni][0], blo[ni][1]);
                    MMA_F16(acc[mi][ni], ahi[mi][0], ahi[mi][1], ahi[mi][2], ahi[mi][3],
                            bhi[ni][0], bhi[ni][1]);
                }
        }
        __syncthreads();
    }

#pragma unroll
    for (int mi = 0; mi < 4; mi++) {
        int row = m0 + wm * 64 + mi * 16 + qr;
#pragma unroll
        for (int ni = 0; ni < 4; ni++) {
            int col = n0 + wn * 32 + ni * 8 + qc * 2;
            if (SPLIT_OUT) {
                uint32_t h, l;
                split2(acc[mi][ni][0], acc[mi][ni][1], h, l);
                *(uint32_t*)&Chi[zC + (long)row * ldc + col] = h;
                *(uint32_t*)&Clo[zC + (long)row * ldc + col] = l;
                split2(acc[mi][ni][2], acc[mi][ni][3], h, l);
                *(uint32_t*)&Chi[zC + (long)(row + 8) * ldc + col] = h;
                *(uint32_t*)&Clo[zC + (long)(row + 8) * ldc + col] = l;
            } else {
                *(float2*)&C[zC + (long)row * ldc + col] =
                    make_float2(acc[mi][ni][0], acc[mi][ni][1]);
                *(float2*)&C[zC + (long)(row + 8) * ldc + col] =
                    make_float2(acc[mi][ni][2], acc[mi][ni][3]);
            }
        }
    }
}

// ---------------------------------------------------------------------------
// Tensor-core causal flash attention. QK 3-product, PV 2-product.
// K(kt+1) prefetch issued right after S consumes K, hiding its latency
// behind softmax + PV. V(kt+1) load issued after PV.
// ---------------------------------------------------------------------------
static constexpr int FA_QHI = 0, FA_QLO = 4608, FA_KHI = 9216, FA_KLO = 13824,
                     FA_VHI = 18432, FA_HALVES = 22528;
static constexpr int FLASH_SMEM = FA_HALVES * 2;   // 45056 B

__global__ void __launch_bounds__(128)
flash_mma(const __half* __restrict__ Qhi, const __half* __restrict__ Qlo,
          const __half* __restrict__ Khi, const __half* __restrict__ Klo,
          const __half* __restrict__ Vhi,
          __half* __restrict__ AOhi, __half* __restrict__ AOlo)
{
    extern __shared__ __half sm[];
    int qt = blockIdx.x, h = blockIdx.y, b = blockIdx.z;
    int q0 = qt * 64;
    int tid = threadIdx.x, w = tid >> 5, lane = tid & 31;
    int qr = lane >> 2, qc = lane & 3;
    int rb = w * 16;

    const long bOff = (long)b * S * D;
    const __half* Qh = Qhi + bOff + (long)q0 * D + h * 64;
    const __half* Ql = Qlo + bOff + (long)q0 * D + h * 64;
    const __half* Kh = Khi + bOff + h * 64;
    const __half* Kl = Klo + bOff + h * 64;
    const __half* Vh = Vhi + bOff + h * 64;

    auto load_q = [&]() {
#pragma unroll
        for (int i = 0; i < 8; i++) {
            int g = tid + i * 128;
            int tsr = g >> 9, rem = g & 511;
            int row = rem >> 3, ch = rem & 7;
            __half* dst = sm + (tsr ? FA_QLO : FA_QHI) + row * 72 + ch * 8;
            const __half* src = (tsr ? Ql : Qh) + (long)row * D + ch * 8;
            CP16(dst, src);
        }
    };
    auto load_k = [&](int kt) {
#pragma unroll
        for (int i = 0; i < 8; i++) {
            int g = tid + i * 128;
            int tsr = g >> 9, rem = g & 511;
            int row = rem >> 3, ch = rem & 7;
            __half* dst = sm + (tsr ? FA_KLO : FA_KHI) + row * 72 + ch * 8;
            const __half* src = (tsr ? Kl : Kh) + (long)(kt * 64 + row) * D + ch * 8;
            CP16(dst, src);
        }
        asm volatile("cp.async.commit_group;" ::: "memory");
    };
    auto load_v = [&](int kt) {
#pragma unroll
        for (int i = 0; i < 4; i++) {
            int g = tid + i * 128;
            int row = g >> 3, ch = g & 7;
            int col = (ch * 8) ^ ((row & 7) << 3);
            __half* dst = sm + FA_VHI + row * 64 + col;
            const __half* src = Vh + (long)(kt * 64 + row) * D + ch * 8;
            CP16(dst, src);
        }
        asm volatile("cp.async.commit_group;" ::: "memory");
    };

    load_q();
    load_k(0);
    load_v(0);
    asm volatile("cp.async.wait_group 0;" ::: "memory");
    __syncthreads();

    uint32_t qa_hi[4][4], qa_lo[4][4];
#pragma unroll
    for (int j = 0; j < 4; j++) {
        int base0 = (rb + qr) * 72 + j * 16 + qc * 2;
#pragma unroll
        for (int r = 0; r < 4; r++) {
            int off = base0 + (r & 1) * 8 * 72 + (r >> 1) * 8;
            qa_hi[j][r] = *(const uint32_t*)&sm[FA_QHI + off];
            qa_lo[j][r] = *(const uint32_t*)&sm[FA_QLO + off];
        }
    }

    float o[8][4];
#pragma unroll
    for (int n = 0; n < 8; n++)
#pragma unroll
        for (int c = 0; c < 4; c++) o[n][c] = 0.f;
    float m0 = -1e30f, m1 = -1e30f, l0 = 0.f, l1 = 0.f;

    const float scale = 0.125f;
    int row0 = q0 + rb + qr, row1 = row0 + 8;
    int nkt = qt + 1;

    for (int kt = 0; kt < nkt; kt++) {
        // ---- S = Q K^T (3-product) ----
        float s[8][4];
#pragma unroll
        for (int n = 0; n < 8; n++)
#pragma unroll
            for (int c = 0; c < 4; c++) s[n][c] = 0.f;

#pragma unroll
        for (int n = 0; n < 8; n++) {
#pragma unroll
            for (int j = 0; j < 4; j++) {
                int base = (n * 8 + qr) * 72 + j * 16 + qc * 2;
                uint32_t bh0 = *(const uint32_t*)&sm[FA_KHI + base];
                uint32_t bh1 = *(const uint32_t*)&sm[FA_KHI + base + 8];
                uint32_t bl0 = *(const uint32_t*)&sm[FA_KLO + base];
                uint32_t bl1 = *(const uint32_t*)&sm[FA_KLO + base + 8];
                MMA_F16(s[n], qa_lo[j][0], qa_lo[j][1], qa_lo[j][2], qa_lo[j][3], bh0, bh1);
                MMA_F16(s[n], qa_hi[j][0], qa_hi[j][1], qa_hi[j][2], qa_hi[j][3], bl0, bl1);
                MMA_F16(s[n], qa_hi[j][0], qa_hi[j][1], qa_hi[j][2], qa_hi[j][3], bh0, bh1);
            }
        }

        // K consumed by all warps; start fetching next K behind softmax+PV
        __syncthreads();
        bool more = (kt + 1 < nkt);
        if (more) load_k(kt + 1);

        // ---- mask + scale + online softmax ----
        float tm0 = -1e30f, tm1 = -1e30f;
#pragma unroll
        for (int n = 0; n < 8; n++) {
            int cb = kt * 64 + n * 8 + qc * 2;
            s[n][0] = (cb     > row0) ? -1e30f : s[n][0] * scale;
            s[n][1] = (cb + 1 > row0) ? -1e30f : s[n][1] * scale;
            s[n][2] = (cb     > row1) ? -1e30f : s[n][2] * scale;
            s[n][3] = (cb + 1 > row1) ? -1e30f : s[n][3] * scale;
            tm0 = fmaxf(tm0, fmaxf(s[n][0], s[n][1]));
            tm1 = fmaxf(tm1, fmaxf(s[n][2], s[n][3]));
        }
        tm0 = fmaxf(tm0, __shfl_xor_sync(0xffffffffu, tm0, 1));
        tm0 = fmaxf(tm0, __shfl_xor_sync(0xffffffffu, tm0, 2));
        tm1 = fmaxf(tm1, __shfl_xor_sync(0xffffffffu, tm1, 1));
        tm1 = fmaxf(tm1, __shfl_xor_sync(0xffffffffu, tm1, 2));

        float mn0 = fmaxf(m0, tm0), mn1 = fmaxf(m1, tm1);
        float al0 = __expf(m0 - mn0), al1 = __expf(m1 - mn1);
        m0 = mn0; m1 = mn1;

        float rs0 = 0.f, rs1 = 0.f;
#pragma unroll
        for (int n = 0; n < 8; n++) {
            s[n][0] = __expf(s[n][0] - mn0);
            s[n][1] = __expf(s[n][1] - mn0);
            s[n][2] = __expf(s[n][2] - mn1);
            s[n][3] = __expf(s[n][3] - mn1);
            rs0 += s[n][0] + s[n][1];
            rs1 += s[n][2] + s[n][3];
        }
        rs0 += __shfl_xor_sync(0xffffffffu, rs0, 1);
        rs0 += __shfl_xor_sync(0xffffffffu, rs0, 2);
        rs1 += __shfl_xor_sync(0xffffffffu, rs1, 1);
        rs1 += __shfl_xor_sync(0xffffffffu, rs1, 2);
        l0 = l0 * al0 + rs0;
        l1 = l1 * al1 + rs1;
#pragma unroll
        for (int n = 0; n < 8; n++) {
            o[n][0] *= al0; o[n][1] *= al0;
            o[n][2] *= al1; o[n][3] *= al1;
        }

        // ---- O += P V_hi (2-product) ----
#pragma unroll
        for (int j = 0; j < 4; j++) {
            uint32_t phi[4], plo[4];
            split2(s[2 * j][0],     s[2 * j][1],     phi[0], plo[0]);
            split2(s[2 * j][2],     s[2 * j][3],     phi[1], plo[1]);
            split2(s[2 * j + 1][0], s[2 * j + 1][1], phi[2], plo[2]);
            split2(s[2 * j + 1][2], s[2 * j + 1][3], phi[3], plo[3]);
            int kr = j * 16 + (lane & 15);
#pragma unroll
            for (int np = 0; np < 4; np++) {
                int nb = np * 16 + (lane >> 4) * 8;
                uint32_t addr_h = (uint32_t)__cvta_generic_to_shared(
                    &sm[FA_VHI + kr * 64 + (nb ^ ((kr & 7) << 3))]);
                uint32_t vh[4];
                asm volatile("ldmatrix.sync.aligned.m8n8.x4.trans.shared.b16 "
                             "{%0,%1,%2,%3}, [%4];"
                             : "=r"(vh[0]), "=r"(vh[1]), "=r"(vh[2]), "=r"(vh[3])
                             : "r"(addr_h));
                int n0i = np * 2, n1i = np * 2 + 1;
                MMA_F16(o[n0i], plo[0], plo[1], plo[2], plo[3], vh[0], vh[1]);
                MMA_F16(o[n0i], phi[0], phi[1], phi[2], phi[3], vh[0], vh[1]);
                MMA_F16(o[n1i], plo[0], plo[1], plo[2], plo[3], vh[2], vh[3]);
                MMA_F16(o[n1i], phi[0], phi[1], phi[2], phi[3], vh[2], vh[3]);
            }
        }

        __syncthreads();          // V consumed by all warps
        if (more) {
            load_v(kt + 1);
            asm volatile("cp.async.wait_group 0;" ::: "memory");
            __syncthreads();
        }
    }

    // ---- epilogue: normalize, split, store ----
    float inv0 = 1.0f / l0, inv1 = 1.0f / l1;
    long obase = bOff + (long)h * 64;
#pragma unroll
    for (int n = 0; n < 8; n++) {
        int col = n * 8 + qc * 2;
        uint32_t hv, lv;
        split2(o[n][0] * inv0, o[n][1] * inv0, hv, lv);
        *(uint32_t*)&AOhi[obase + (long)row0 * D + col] = hv;
        *(uint32_t*)&AOlo[obase + (long)row0 * D + col] = lv;
        split2(o[n][2] * inv1, o[n][3] * inv1, hv, lv);
        *(uint32_t*)&AOhi[obase + (long)row1 * D + col] = hv;
        *(uint32_t*)&AOlo[obase + (long)row1 * D + col] = lv;
    }
}

// ---------------------------------------------------------------------------
// Host entry
// ---------------------------------------------------------------------------
extern "C" void kernel_launch(void* const* d_in, const int* in_sizes, int n_in,
                              void* d_out, int out_size)
{
    const float* x    = (const float*)d_in[0];
    const float* cw   = (const float*)d_in[1];
    const int*   ci   = (const int*)  d_in[2];
    const float* wq   = (const float*)d_in[3];
    const int*   iq   = (const int*)  d_in[4];
    const float* wk   = (const float*)d_in[5];
    const int*   ik   = (const int*)  d_in[6];
    const float* wv   = (const float*)d_in[7];
    const int*   iv   = (const int*)  d_in[8];
    const float* cn   = (const float*)d_in[9];
    const float* pool = (const float*)d_in[10];
    const float* WO   = (const float*)d_in[11];
    float* out = (float*)d_out;

    float* base = nullptr;
    cudaGetSymbolAddress((void**)&base, g_scratch);

    __half* hb    = (__half*)base;
    __half* xhi   = hb;               __half* xlo   = xhi   + N_QKV;
    __half* WcThi = xlo   + N_QKV;    __half* WcTlo = WcThi + N_WC;
    __half* WqThi = WcTlo + N_WC;     __half* WqTlo = WqThi + 3 * N_WX;
    __half* hhi   = WqTlo + 3 * N_WX; __half* hlo   = hhi   + N_H;
    __half* Qhi   = hlo   + N_H;      __half* Qlo   = Qhi   + N_QKV;
    __half* Khi   = Qlo   + N_QKV;    __half* Klo   = Khi   + N_QKV;
    __half* Vhi   = Klo   + N_QKV;    __half* Vlo   = Vhi   + N_QKV;
    __half* AOhi  = Vlo   + N_QKV;    __half* AOlo  = AOhi  + N_QKV;
    __half* WOhi  = AOlo  + N_QKV;    __half* WOlo  = WOhi  + N_WO;

    cudaFuncSetAttribute(hgemm<3, true>,
                         cudaFuncAttributeMaxDynamicSharedMemorySize, GEMM_SMEM);
    cudaFuncSetAttribute(hgemm<2, true>,
                         cudaFuncAttributeMaxDynamicSharedMemorySize, GEMM_SMEM);
    cudaFuncSetAttribute(hgemm<2, false>,
                         cudaFuncAttributeMaxDynamicSharedMemorySize, GEMM_SMEM);
    cudaFuncSetAttribute(flash_mma,
                         cudaFuncAttributeMaxDynamicSharedMemorySize, FLASH_SMEM);

    // 1) fused combines -> transposed fp16 hi/lo weights
    combine_compress_T<<<dim3(D / 32, B), 256>>>(cw, ci, cn, WcThi, WcTlo);
    combine_expand_T<<<dim3(D / 32, B, 3), 256>>>(wq, iq, wk, ik, wv, iv, pool,
                                                  WqThi, WqTlo);

    // 2) splits of inputs
    split_kernel<<<(int)(N_QKV / 1024), 256>>>(x, xhi, xlo);
    split_kernel<<<(int)(N_WO  / 1024), 256>>>(WO, WOhi, WOlo);

    // 3) h = x @ WcT^T (3-product)
    hgemm<3, true><<<dim3(1, S / 128, B), 256, GEMM_SMEM>>>(
        xhi, xlo, WcThi, WcTlo, nullptr, hhi, hlo,
        D, D, D, R, (long)S * D, (long)R * D, (long)S * R);

    // 4) Q/K 3-product; V 2-product
    hgemm<3, true><<<dim3(D / 128, S / 128, B), 256, GEMM_SMEM>>>(
        hhi, hlo, WqThi, WqTlo, nullptr, Qhi, Qlo,
        R, R, R, D, (long)S * R, (long)D * R, (long)S * D);
    hgemm<3, true><<<dim3(D / 128, S / 128, B), 256, GEMM_SMEM>>>(
        hhi, hlo, WqThi + N_WX, WqTlo + N_WX, nullptr, Khi, Klo,
        R, R, R, D, (long)S * R, (long)D * R, (long)S * D);
    hgemm<2, true><<<dim3(D / 128, S / 128, B), 256, GEMM_SMEM>>>(
        hhi, hlo, WqThi + 2 * N_WX, WqTlo + 2 * N_WX, nullptr, Vhi, Vlo,
        R, R, R, D, (long)S * R, (long)D * R, (long)S * D);

    // 5) flash attention (K-prefetch pipelined)
    flash_mma<<<dim3(S / 64, H, B), 128, FLASH_SMEM>>>(
        Qhi, Qlo, Khi, Klo, Vhi, AOhi, AOlo);

    // 6) out = AO @ W_O^T (2-product)
    hgemm<2, false><<<dim3(D / 128, (B * S) / 128, 1), 256, GEMM_SMEM>>>(
        AOhi, AOlo, WOhi, WOlo, out, nullptr, nullptr,
        D, D, D, D, 0, 0, 0);
}

// round 14
// speedup vs baseline: 1.0299x; 1.0299x over previous
#include <cuda_runtime.h>
#include <cuda_fp16.h>
#include <cstdint>

// ---------------------------------------------------------------------------
// Problem constants
// ---------------------------------------------------------------------------
static constexpr int B   = 8;
static constexpr int S   = 1024;
static constexpr int D   = 1024;
static constexpr int H   = 16;
static constexpr int DH  = 64;
static constexpr int R   = 128;   // RANK
static constexpr int KC  = 16;
static constexpr int KE  = 8;

// ---------------------------------------------------------------------------
// Scratch layout (fp16 hi/lo pairs)
// ---------------------------------------------------------------------------
static constexpr size_t N_WC  = (size_t)B * D * R;
static constexpr size_t N_H   = (size_t)B * S * R;
static constexpr size_t N_WX  = (size_t)B * R * D;
static constexpr size_t N_QKV = (size_t)B * S * D;
static constexpr size_t N_WO  = (size_t)D * D;
static constexpr size_t HALVES =
    10 * N_QKV + 2 * N_WC + 6 * N_WX + 2 * N_H + 2 * N_WO;
static constexpr size_t SCRATCH_FLOATS = (HALVES + 1) / 2;

__device__ __align__(1024) float g_scratch[SCRATCH_FLOATS];

// ---------------------------------------------------------------------------
// Helpers
// ---------------------------------------------------------------------------
__device__ __forceinline__ void split2(float a, float b, uint32_t& hi, uint32_t& lo) {
    __half2 h = __floats2half2_rn(a, b);
    hi = *reinterpret_cast<uint32_t*>(&h);
    float2 f = __half22float2(h);
    __half2 l = __floats2half2_rn(a - f.x, b - f.y);
    lo = *reinterpret_cast<uint32_t*>(&l);
}

#define MMA_F16(ACC, A0, A1, A2, A3, B0, B1)                                   \
    asm volatile("mma.sync.aligned.m16n8k16.row.col.f32.f16.f16.f32 "          \
        "{%0,%1,%2,%3}, {%4,%5,%6,%7}, {%8,%9}, {%0,%1,%2,%3};"                \
        : "+f"((ACC)[0]), "+f"((ACC)[1]), "+f"((ACC)[2]), "+f"((ACC)[3])       \
        : "r"(A0), "r"(A1), "r"(A2), "r"(A3), "r"(B0), "r"(B1))

#define CP16(dst_half_ptr, src_ptr)                                            \
    asm volatile("cp.async.cg.shared.global [%0], [%1], 16;"                   \
        :: "r"((uint32_t)__cvta_generic_to_shared(dst_half_ptr)), "l"(src_ptr))

// ---------------------------------------------------------------------------
// Fused: compress combine -> transpose -> fp16 hi/lo split.
// Out: WcT[b][r][d] hi/lo. grid (D/32, B), 256 threads.
// ---------------------------------------------------------------------------
__global__ void combine_compress_T(const float* __restrict__ w,
                                   const int*   __restrict__ idx,
                                   const float* __restrict__ cn,
                                   __half* __restrict__ ohi,
                                   __half* __restrict__ olo)
{
    int dt = blockIdx.x * 32;
    int b  = blockIdx.y;
    __shared__ float s[32][129];
    __shared__ float sw[KC];
    __shared__ int   si[KC];
    int tid = threadIdx.x;
    if (tid < KC) { sw[tid] = w[b * KC + tid]; si[tid] = idx[b * KC + tid]; }
    __syncthreads();

    float a[16];
#pragma unroll
    for (int j = 0; j < 16; j++) a[j] = 0.f;
#pragma unroll
    for (int k = 0; k < KC; k++) {
        const float* src = cn + ((long)si[k] * D + dt) * R;
        float wk = sw[k];
#pragma unroll
        for (int j = 0; j < 16; j++)
            a[j] += wk * src[tid + j * 256];
    }
#pragma unroll
    for (int j = 0; j < 16; j++) {
        int i = tid + j * 256;            // d = i>>7, r = i&127
        s[i >> 7][i & 127] = a[j];
    }
    __syncthreads();

    int r = tid >> 1, dp = (tid & 1) * 16;
    uint32_t hb[8], lb[8];
#pragma unroll
    for (int p = 0; p < 8; p++)
        split2(s[dp + 2 * p][r], s[dp + 2 * p + 1][r], hb[p], lb[p]);
    long o = ((long)b * R + r) * D + dt + dp;
    ((uint4*)&ohi[o])[0] = ((uint4*)hb)[0];
    ((uint4*)&ohi[o])[1] = ((uint4*)hb)[1];
    ((uint4*)&olo[o])[0] = ((uint4*)lb)[0];
    ((uint4*)&olo[o])[1] = ((uint4*)lb)[1];
}

// ---------------------------------------------------------------------------
// Fused: expand combine -> transpose -> fp16 hi/lo split.
// Out layout for FUSED QKV gemm: W[(b*3+mat)*D + d][r].
// grid (D/32, B, 3), 256 threads.
// ---------------------------------------------------------------------------
__global__ void combine_expand_T(const float* __restrict__ wq, const int* __restrict__ iq,
                                 const float* __restrict__ wk, const int* __restrict__ ik,
                                 const float* __restrict__ wv, const int* __restrict__ iv,
                                 const float* __restrict__ pool,
                                 __half* __restrict__ Whi, __half* __restrict__ Wlo)
{
    int dt  = blockIdx.x * 32;
    int b   = blockIdx.y;
    int mat = blockIdx.z;
    const float* w  = (mat == 0) ? wq : (mat == 1) ? wk : wv;
    const int*   id = (mat == 0) ? iq : (mat == 1) ? ik : iv;

    __shared__ float s[32][129];          // s[dd][r]
    __shared__ float sw[KE];
    __shared__ int   si[KE];
    int tid = threadIdx.x;
    if (tid < KE) { sw[tid] = w[b * KE + tid]; si[tid] = id[b * KE + tid]; }
    __syncthreads();

    float a[16];
#pragma unroll
    for (int j = 0; j < 16; j++) a[j] = 0.f;
#pragma unroll
    for (int k = 0; k < KE; k++) {
        const float* src = pool + (long)si[k] * R * D + dt;
        float wk_ = sw[k];
#pragma unroll
        for (int j = 0; j < 16; j++) {
            int i = tid + j * 256;        // r = i>>5, dd = i&31
            a[j] += wk_ * src[(long)(i >> 5) * D + (i & 31)];
        }
    }
#pragma unroll
    for (int j = 0; j < 16; j++) {
        int i = tid + j * 256;
        s[i & 31][i >> 5] = a[j];
    }
    __syncthreads();

    int d = tid >> 3, rp = (tid & 7) * 16;
    uint32_t hb[8], lb[8];
#pragma unroll
    for (int p = 0; p < 8; p++)
        split2(s[d][rp + 2 * p], s[d][rp + 2 * p + 1], hb[p], lb[p]);
    long o = ((long)(b * 3 + mat) * D + dt + d) * R + rp;   // batch-major, mat inner
    ((uint4*)&Whi[o])[0] = ((uint4*)hb)[0];
    ((uint4*)&Whi[o])[1] = ((uint4*)hb)[1];
    ((uint4*)&Wlo[o])[0] = ((uint4*)lb)[0];
    ((uint4*)&Wlo[o])[1] = ((uint4*)lb)[1];
}

// ---------------------------------------------------------------------------
// fp32 -> fp16 hi/lo elementwise
// ---------------------------------------------------------------------------
__global__ void split_kernel(const float* __restrict__ in,
                             __half* __restrict__ hi, __half* __restrict__ lo)
{
    long i = ((long)blockIdx.x * 256 + threadIdx.x) * 4;
    float4 v = *(const float4*)&in[i];
    uint32_t h0, l0, h1, l1;
    split2(v.x, v.y, h0, l0);
    split2(v.z, v.w, h1, l1);
    *(uint2*)&hi[i] = make_uint2(h0, h1);
    *(uint2*)&lo[i] = make_uint2(l0, l1);
}

// ---------------------------------------------------------------------------
// fp16-pair tensor-core GEMM, 128x128x32 tiles, 256 threads.
// ---------------------------------------------------------------------------
static constexpr int TILE_H    = 128 * 40;
static constexpr int GEMM_SMEM = 2 * 4 * TILE_H * 2;  // 81920 B

template <int NPROD, bool SPLIT_OUT>
__global__ void __launch_bounds__(256)
hgemm(const __half* __restrict__ Ahi, const __half* __restrict__ Alo,
      const __half* __restrict__ Bhi, const __half* __restrict__ Blo,
      float* __restrict__ C, __half* __restrict__ Chi, __half* __restrict__ Clo,
      int K, int lda, int ldb, int ldc, long sA, long sB, long sC)
{
    extern __shared__ __half sm[];
    int tid = threadIdx.x, wid = tid >> 5, lane = tid & 31;
    int wm = wid & 1, wn = wid >> 1;
    int qr = lane >> 2, qc = lane & 3;

    long zA = (long)blockIdx.z * sA, zB = (long)blockIdx.z * sB, zC = (long)blockIdx.z * sC;
    int m0 = blockIdx.y * 128, n0 = blockIdx.x * 128;

    const __half* srcs[4] = { Ahi + zA, Alo + zA, Bhi + zB, Blo + zB };
    int rbase[4] = { m0, m0, n0, n0 };
    int lds[4]   = { lda, lda, ldb, ldb };

    float acc[4][4][4];
#pragma unroll
    for (int mi = 0; mi < 4; mi++)
#pragma unroll
        for (int ni = 0; ni < 4; ni++)
#pragma unroll
            for (int c = 0; c < 4; c++) acc[mi][ni][c] = 0.f;

    int nt = K / 32;
    constexpr int NLOAD = (NPROD == 3) ? 8 : 6;

    auto load_stage = [&](int kt, int st) {
        __half* sb = sm + st * 4 * TILE_H;
#pragma unroll
        for (int i = 0; i < NLOAD; i++) {
            int g = tid + i * 256;
            int tsr = g >> 9;
            int rem = g & 511;
            int row = rem >> 2, ch = rem & 3;
            __half* dst = sb + tsr * TILE_H + row * 40 + ch * 8;
            const __half* src = srcs[tsr] + (long)(rbase[tsr] + row) * lds[tsr]
                                + kt * 32 + ch * 8;
            CP16(dst, src);
        }
        asm volatile("cp.async.commit_group;" ::: "memory");
    };

    load_stage(0, 0);

    for (int kt = 0; kt < nt; kt++) {
        if (kt + 1 < nt) {
            load_stage(kt + 1, (kt + 1) & 1);
            asm volatile("cp.async.wait_group 1;" ::: "memory");
        } else {
            asm volatile("cp.async.wait_group 0;" ::: "memory");
        }
        __syncthreads();

        const __half* sb = sm + (kt & 1) * 4 * TILE_H;
        const __half* As_hi = sb;
        const __half* As_lo = sb + TILE_H;
        const __half* Bs_hi = sb + 2 * TILE_H;
        const __half* Bs_lo = sb + 3 * TILE_H;

#pragma unroll
        for (int ks = 0; ks < 2; ks++) {
            uint32_t ahi[4][4], alo[4][4];
#pragma unroll
            for (int mi = 0; mi < 4; mi++) {
                int base = (wm * 64 + mi * 16 + qr) * 40 + ks * 16 + qc * 2;
                ahi[mi][0] = *(const uint32_t*)&As_hi[base];
                ahi[mi][1] = *(const uint32_t*)&As_hi[base + 8 * 40];
                ahi[mi][2] = *(const uint32_t*)&As_hi[base + 8];
                ahi[mi][3] = *(const uint32_t*)&As_hi[base + 8 * 40 + 8];
                alo[mi][0] = *(const uint32_t*)&As_lo[base];
                alo[mi][1] = *(const uint32_t*)&As_lo[base + 8 * 40];
                alo[mi][2] = *(const uint32_t*)&As_lo[base + 8];
                alo[mi][3] = *(const uint32_t*)&As_lo[base + 8 * 40 + 8];
            }
            uint32_t bhi[4][2], blo[4][2];
#pragma unroll
            for (int ni = 0; ni < 4; ni++) {
                int base = (wn * 32 + ni * 8 + qr) * 40 + ks * 16 + qc * 2;
                bhi[ni][0] = *(const uint32_t*)&Bs_hi[base];
                bhi[ni][1] = *(const uint32_t*)&Bs_hi[base + 8];
                if (NPROD == 3) {
                    blo[ni][0] = *(const uint32_t*)&Bs_lo[base];
                    blo[ni][1] = *(const uint32_t*)&Bs_lo[base + 8];
                }
            }
#pragma unroll
            for (int mi = 0; mi < 4; mi++)
#pragma unroll
                for (int ni = 0; ni < 4; ni++) {
                    MMA_F16(acc[mi][ni], alo[mi][0], alo[mi][1], alo[mi][2], alo[mi][3],
                            bhi[ni][0], bhi[ni][1]);
                    if (NPROD == 3)
                        MMA_F16(acc[mi][ni], ahi[mi][0], ahi[mi][1], ahi[mi][2], ahi[mi][3],
                                blo[ni][0], blo[ni][1]);
                    MMA_F16(acc[mi][ni], ahi[mi][0], ahi[mi][1], ahi[mi][2], ahi[mi][3],
                            bhi[ni][0], bhi[ni][1]);
                }
        }
        __syncthreads();
    }

#pragma unroll
    for (int mi = 0; mi < 4; mi++) {
        int row = m0 + wm * 64 + mi * 16 + qr;
#pragma unroll
        for (int ni = 0; ni < 4; ni++) {
            int col = n0 + wn * 32 + ni * 8 + qc * 2;
            if (SPLIT_OUT) {
                uint32_t h, l;
                split2(acc[mi][ni][0], acc[mi][ni][1], h, l);
                *(uint32_t*)&Chi[zC + (long)row * ldc + col] = h;
                *(uint32_t*)&Clo[zC + (long)row * ldc + col] = l;
                split2(acc[mi][ni][2], acc[mi][ni][3], h, l);
                *(uint32_t*)&Chi[zC + (long)(row + 8) * ldc + col] = h;
                *(uint32_t*)&Clo[zC + (long)(row + 8) * ldc + col] = l;
            } else {
                *(float2*)&C[zC + (long)row * ldc + col] =
                    make_float2(acc[mi][ni][0], acc[mi][ni][1]);
                *(float2*)&C[zC + (long)(row + 8) * ldc + col] =
                    make_float2(acc[mi][ni][2], acc[mi][ni][3]);
            }
        }
    }
}

// ---------------------------------------------------------------------------
// 64x64x32-tile variant (128 threads, 2Mx2N warps, warp tile 32x32).
// For small-grid GEMMs (h) to fill the 148-SM chip.
// ---------------------------------------------------------------------------
static constexpr int TILE64_H    = 64 * 40;
static constexpr int GEMM64_SMEM = 2 * 4 * TILE64_H * 2;  // 40960 B

template <int NPROD, bool SPLIT_OUT>
__global__ void __launch_bounds__(128)
hgemm64(const __half* __restrict__ Ahi, const __half* __restrict__ Alo,
        const __half* __restrict__ Bhi, const __half* __restrict__ Blo,
        float* __restrict__ C, __half* __restrict__ Chi, __half* __restrict__ Clo,
        int K, int lda, int ldb, int ldc, long sA, long sB, long sC)
{
    extern __shared__ __half sm[];
    int tid = threadIdx.x, wid = tid >> 5, lane = tid & 31;
    int wm = wid & 1, wn = wid >> 1;       // 2 x 2 warps
    int qr = lane >> 2, qc = lane & 3;

    long zA = (long)blockIdx.z * sA, zB = (long)blockIdx.z * sB, zC = (long)blockIdx.z * sC;
    int m0 = blockIdx.y * 64, n0 = blockIdx.x * 64;

    const __half* srcs[4] = { Ahi + zA, Alo + zA, Bhi + zB, Blo + zB };
    int rbase[4] = { m0, m0, n0, n0 };
    int lds[4]   = { lda, lda, ldb, ldb };

    float acc[2][4][4];
#pragma unroll
    for (int mi = 0; mi < 2; mi++)
#pragma unroll
        for (int ni = 0; ni < 4; ni++)
#pragma unroll
            for (int c = 0; c < 4; c++) acc[mi][ni][c] = 0.f;

    int nt = K / 32;
    constexpr int NLOAD = (NPROD == 3) ? 8 : 6;   // x128 threads over 256/tensor

    auto load_stage = [&](int kt, int st) {
        __half* sb = sm + st * 4 * TILE64_H;
#pragma unroll
        for (int i = 0; i < NLOAD; i++) {
            int g = tid + i * 128;
            int tsr = g >> 8;
            int rem = g & 255;
            int row = rem >> 2, ch = rem & 3;
            __half* dst = sb + tsr * TILE64_H + row * 40 + ch * 8;
            const __half* src = srcs[tsr] + (long)(rbase[tsr] + row) * lds[tsr]
                                + kt * 32 + ch * 8;
            CP16(dst, src);
        }
        asm volatile("cp.async.commit_group;" ::: "memory");
    };

    load_stage(0, 0);

    for (int kt = 0; kt < nt; kt++) {
        if (kt + 1 < nt) {
            load_stage(kt + 1, (kt + 1) & 1);
            asm volatile("cp.async.wait_group 1;" ::: "memory");
        } else {
            asm volatile("cp.async.wait_group 0;" ::: "memory");
        }
        __syncthreads();

        const __half* sb = sm + (kt & 1) * 4 * TILE64_H;
        const __half* As_hi = sb;
        const __half* As_lo = sb + TILE64_H;
        const __half* Bs_hi = sb + 2 * TILE64_H;
        const __half* Bs_lo = sb + 3 * TILE64_H;

#pragma unroll
        for (int ks = 0; ks < 2; ks++) {
            uint32_t ahi[2][4], alo[2][4];
#pragma unroll
            for (int mi = 0; mi < 2; mi++) {
                int base = (wm * 32 + mi * 16 + qr) * 40 + ks * 16 + qc * 2;
                ahi[mi][0] = *(const uint32_t*)&As_hi[base];
                ahi[mi][1] = *(const uint32_t*)&As_hi[base + 8 * 40];
                ahi[mi][2] = *(const uint32_t*)&As_hi[base + 8];
                ahi[mi][3] = *(const uint32_t*)&As_hi[base + 8 * 40 + 8];
                alo[mi][0] = *(const uint32_t*)&As_lo[base];
                alo[mi][1] = *(const uint32_t*)&As_lo[base + 8 * 40];
                alo[mi][2] = *(const uint32_t*)&As_lo[base + 8];
                alo[mi][3] = *(const uint32_t*)&As_lo[base + 8 * 40 + 8];
            }
            uint32_t bhi[4][2], blo[4][2];
#pragma unroll
            for (int ni = 0; ni < 4; ni++) {
                int base = (wn * 32 + ni * 8 + qr) * 40 + ks * 16 + qc * 2;
                bhi[ni][0] = *(const uint32_t*)&Bs_hi[base];
                bhi[ni][1] = *(const uint32_t*)&Bs_hi[base + 8];
                if (NPROD == 3) {
                    blo[ni][0] = *(const uint32_t*)&Bs_lo[base];
                    blo[ni][1] = *(const uint32_t*)&Bs_lo[base + 8];
                }
            }
#pragma unroll
            for (int mi = 0; mi < 2; mi++)
#pragma unroll
                for (int ni = 0; ni < 4; ni++) {
                    MMA_F16(acc[mi][ni], alo[mi][0], alo[mi][1], alo[mi][2], alo[mi][3],
                            bhi[ni][0], bhi[ni][1]);
                    if (NPROD == 3)
                        MMA_F16(acc[mi][ni], ahi[mi][0], ahi[mi][1], ahi[mi][2], ahi[mi][3],
                                blo[ni][0], blo[ni][1]);
                    MMA_F16(acc[mi][ni], ahi[mi][0], ahi[mi][1], ahi[mi][2], ahi[mi][3],
                            bhi[ni][0], bhi[ni][1]);
                }
        }
        __syncthreads();
    }

#pragma unroll
    for (int mi = 0; mi < 2; mi++) {
        int row = m0 + wm * 32 + mi * 16 + qr;
#pragma unroll
        for (int ni = 0; ni < 4; ni++) {
            int col = n0 + wn * 32 + ni * 8 + qc * 2;
            if (SPLIT_OUT) {
                uint32_t h, l;
                split2(acc[mi][ni][0], acc[mi][ni][1], h, l);
                *(uint32_t*)&Chi[zC + (long)row * ldc + col] = h;
                *(uint32_t*)&Clo[zC + (long)row * ldc + col] = l;
                split2(acc[mi][ni][2], acc[mi][ni][3], h, l);
                *(uint32_t*)&Chi[zC + (long)(row + 8) * ldc + col] = h;
                *(uint32_t*)&Clo[zC + (long)(row + 8) * ldc + col] = l;
            } else {
                *(float2*)&C[zC + (long)row * ldc + col] =
                    make_float2(acc[mi][ni][0], acc[mi][ni][1]);
                *(float2*)&C[zC + (long)(row + 8) * ldc + col] =
                    make_float2(acc[mi][ni][2], acc[mi][ni][3]);
            }
        }
    }
}

// ---------------------------------------------------------------------------
// Tensor-core causal flash attention. QK 3-product, PV 2-product.
// Q/K/V live in the fused QKV buffer: row stride 3D, col offsets {0,D,2D}.
// ---------------------------------------------------------------------------
static constexpr int LDQKV = 3 * D;
static constexpr int FA_QHI = 0, FA_QLO = 4608, FA_KHI = 9216, FA_KLO = 13824,
                     FA_VHI = 18432, FA_HALVES = 22528;
static constexpr int FLASH_SMEM = FA_HALVES * 2;   // 45056 B

__global__ void __launch_bounds__(128)
flash_mma(const __half* __restrict__ QKVhi, const __half* __restrict__ QKVlo,
          __half* __restrict__ AOhi, __half* __restrict__ AOlo)
{
    extern __shared__ __half sm[];
    int qt = blockIdx.x, h = blockIdx.y, b = blockIdx.z;
    int q0 = qt * 64;
    int tid = threadIdx.x, w = tid >> 5, lane = tid & 31;
    int qr = lane >> 2, qc = lane & 3;
    int rb = w * 16;

    const long bQKV = (long)b * S * LDQKV;
    const __half* Qh = QKVhi + bQKV + (long)q0 * LDQKV + h * 64;
    const __half* Ql = QKVlo + bQKV + (long)q0 * LDQKV + h * 64;
    const __half* Kh = QKVhi + bQKV + D + h * 64;
    const __half* Kl = QKVlo + bQKV + D + h * 64;
    const __half* Vh = QKVhi + bQKV + 2 * D + h * 64;

    auto load_q = [&]() {
#pragma unroll
        for (int i = 0; i < 8; i++) {
            int g = tid + i * 128;
            int tsr = g >> 9, rem = g & 511;
            int row = rem >> 3, ch = rem & 7;
            __half* dst = sm + (tsr ? FA_QLO : FA_QHI) + row * 72 + ch * 8;
            const __half* src = (tsr ? Ql : Qh) + (long)row * LDQKV + ch * 8;
            CP16(dst, src);
        }
    };
    auto load_k = [&](int kt) {
#pragma unroll
        for (int i = 0; i < 8; i++) {
            int g = tid + i * 128;
            int tsr = g >> 9, rem = g & 511;
            int row = rem >> 3, ch = rem & 7;
            __half* dst = sm + (tsr ? FA_KLO : FA_KHI) + row * 72 + ch * 8;
            const __half* src = (tsr ? Kl : Kh) + (long)(kt * 64 + row) * LDQKV + ch * 8;
            CP16(dst, src);
        }
        asm volatile("cp.async.commit_group;" ::: "memory");
    };
    auto load_v = [&](int kt) {
#pragma unroll
        for (int i = 0; i < 4; i++) {
            int g = tid + i * 128;
            int row = g >> 3, ch = g & 7;
            int col = (ch * 8) ^ ((row & 7) << 3);
            __half* dst = sm + FA_VHI + row * 64 + col;
            const __half* src = Vh + (long)(kt * 64 + row) * LDQKV + ch * 8;
            CP16(dst, src);
        }
        asm volatile("cp.async.commit_group;" ::: "memory");
    };

    load_q();
    load_k(0);
    load_v(0);
    asm volatile("cp.async.wait_group 0;" ::: "memory");
    __syncthreads();

    uint32_t qa_hi[4][4], qa_lo[4][4];
#pragma unroll
    for (int j = 0; j < 4; j++) {
        int base0 = (rb + qr) * 72 + j * 16 + qc * 2;
#pragma unroll
        for (int r = 0; r < 4; r++) {
            int off = base0 + (r & 1) * 8 * 72 + (r >> 1) * 8;
            qa_hi[j][r] = *(const uint32_t*)&sm[FA_QHI + off];
            qa_lo[j][r] = *(const uint32_t*)&sm[FA_QLO + off];
        }
    }

    float o[8][4];
#pragma unroll
    for (int n = 0; n < 8; n++)
#pragma unroll
        for (int c = 0; c < 4; c++) o[n][c] = 0.f;
    float m0 = -1e30f, m1 = -1e30f, l0 = 0.f, l1 = 0.f;

    const float scale = 0.125f;
    int row0 = q0 + rb + qr, row1 = row0 + 8;
    int nkt = qt + 1;

    for (int kt = 0; kt < nkt; kt++) {
        float s[8][4];
#pragma unroll
        for (int n = 0; n < 8; n++)
#pragma unroll
            for (int c = 0; c < 4; c++) s[n][c] = 0.f;

#pragma unroll
        for (int n = 0; n < 8; n++) {
#pragma unroll
            for (int j = 0; j < 4; j++) {
                int base = (n * 8 + qr) * 72 + j * 16 + qc * 2;
                uint32_t bh0 = *(const uint32_t*)&sm[FA_KHI + base];
                uint32_t bh1 = *(const uint32_t*)&sm[FA_KHI + base + 8];
                uint32_t bl0 = *(const uint32_t*)&sm[FA_KLO + base];
                uint32_t bl1 = *(const uint32_t*)&sm[FA_KLO + base + 8];
                MMA_F16(s[n], qa_lo[j][0], qa_lo[j][1], qa_lo[j][2], qa_lo[j][3], bh0, bh1);
                MMA_F16(s[n], qa_hi[j][0], qa_hi[j][1], qa_hi[j][2], qa_hi[j][3], bl0, bl1);
                MMA_F16(s[n], qa_hi[j][0], qa_hi[j][1], qa_hi[j][2], qa_hi[j][3], bh0, bh1);
            }
        }

        __syncthreads();
        bool more = (kt + 1 < nkt);
        if (more) load_k(kt + 1);

        float tm0 = -1e30f, tm1 = -1e30f;
#pragma unroll
        for (int n = 0; n < 8; n++) {
            int cb = kt * 64 + n * 8 + qc * 2;
            s[n][0] = (cb     > row0) ? -1e30f : s[n][0] * scale;
            s[n][1] = (cb + 1 > row0) ? -1e30f : s[n][1] * scale;
            s[n][2] = (cb     > row1) ? -1e30f : s[n][2] * scale;
            s[n][3] = (cb + 1 > row1) ? -1e30f : s[n][3] * scale;
            tm0 = fmaxf(tm0, fmaxf(s[n][0], s[n][1]));
            tm1 = fmaxf(tm1, fmaxf(s[n][2], s[n][3]));
        }
        tm0 = fmaxf(tm0, __shfl_xor_sync(0xffffffffu, tm0, 1));
        tm0 = fmaxf(tm0, __shfl_xor_sync(0xffffffffu, tm0, 2));
        tm1 = fmaxf(tm1, __shfl_xor_sync(0xffffffffu, tm1, 1));
        tm1 = fmaxf(tm1, __shfl_xor_sync(0xffffffffu, tm1, 2));

        float mn0 = fmaxf(m0, tm0), mn1 = fmaxf(m1, tm1);
        float al0 = __expf(m0 - mn0), al1 = __expf(m1 - mn1);
        m0 = mn0; m1 = mn1;

        float rs0 = 0.f, rs1 = 0.f;
#pragma unroll
        for (int n = 0; n < 8; n++) {
            s[n][0] = __expf(s[n][0] - mn0);
            s[n][1] = __expf(s[n][1] - mn0);
            s[n][2] = __expf(s[n][2] - mn1);
            s[n][3] = __expf(s[n][3] - mn1);
            rs0 += s[n][0] + s[n][1];
            rs1 += s[n][2] + s[n][3];
        }
        rs0 += __shfl_xor_sync(0xffffffffu, rs0, 1);
        rs0 += __shfl_xor_sync(0xffffffffu, rs0, 2);
        rs1 += __shfl_xor_sync(0xffffffffu, rs1, 1);
        rs1 += __shfl_xor_sync(0xffffffffu, rs1, 2);
        l0 = l0 * al0 + rs0;
        l1 = l1 * al1 + rs1;
#pragma unroll
        for (int n = 0; n < 8; n++) {
            o[n][0] *= al0; o[n][1] *= al0;
            o[n][2] *= al1; o[n][3] *= al1;
        }

#pragma unroll
        for (int j = 0; j < 4; j++) {
            uint32_t phi[4], plo[4];
            split2(s[2 * j][0],     s[2 * j][1],     phi[0], plo[0]);
            split2(s[2 * j][2],     s[2 * j][3],     phi[1], plo[1]);
            split2(s[2 * j + 1][0], s[2 * j + 1][1], phi[2], plo[2]);
            split2(s[2 * j + 1][2], s[2 * j + 1][3], phi[3], plo[3]);
            int kr = j * 16 + (lane & 15);
#pragma unroll
            for (int np = 0; np < 4; np++) {
                int nb = np * 16 + (lane >> 4) * 8;
                uint32_t addr_h = (uint32_t)__cvta_generic_to_shared(
                    &sm[FA_VHI + kr * 64 + (nb ^ ((kr & 7) << 3))]);
                uint32_t vh[4];
                asm volatile("ldmatrix.sync.aligned.m8n8.x4.trans.shared.b16 "
                             "{%0,%1,%2,%3}, [%4];"
                             : "=r"(vh[0]), "=r"(vh[1]), "=r"(vh[2]), "=r"(vh[3])
                             : "r"(addr_h));
                int n0i = np * 2, n1i = np * 2 + 1;
                MMA_F16(o[n0i], plo[0], plo[1], plo[2], plo[3], vh[0], vh[1]);
                MMA_F16(o[n0i], phi[0], phi[1], phi[2], phi[3], vh[0], vh[1]);
                MMA_F16(o[n1i], plo[0], plo[1], plo[2], plo[3], vh[2], vh[3]);
                MMA_F16(o[n1i], phi[0], phi[1], phi[2], phi[3], vh[2], vh[3]);
            }
        }

        __syncthreads();
        if (more) {
            load_v(kt + 1);
            asm volatile("cp.async.wait_group 0;" ::: "memory");
            __syncthreads();
        }
    }

    float inv0 = 1.0f / l0, inv1 = 1.0f / l1;
    long obase = (long)b * S * D + (long)h * 64;
#pragma unroll
    for (int n = 0; n < 8; n++) {
        int col = n * 8 + qc * 2;
        uint32_t hv, lv;
        split2(o[n][0] * inv0, o[n][1] * inv0, hv, lv);
        *(uint32_t*)&AOhi[obase + (long)row0 * D + col] = hv;
        *(uint32_t*)&AOlo[obase + (long)row0 * D + col] = lv;
        split2(o[n][2] * inv1, o[n][3] * inv1, hv, lv);
        *(uint32_t*)&AOhi[obase + (long)row1 * D + col] = hv;
        *(uint32_t*)&AOlo[obase + (long)row1 * D + col] = lv;
    }
}

// ---------------------------------------------------------------------------
// Host entry
// ---------------------------------------------------------------------------
extern "C" void kernel_launch(void* const* d_in, const int* in_sizes, int n_in,
                              void* d_out, int out_size)
{
    const float* x    = (const float*)d_in[0];
    const float* cw   = (const float*)d_in[1];
    const int*   ci   = (const int*)  d_in[2];
    const float* wq   = (const float*)d_in[3];
    const int*   iq   = (const int*)  d_in[4];
    const float* wk   = (const float*)d_in[5];
    const int*   ik   = (const int*)  d_in[6];
    const float* wv   = (const float*)d_in[7];
    const int*   iv   = (const int*)  d_in[8];
    const float* cn   = (const float*)d_in[9];
    const float* pool = (const float*)d_in[10];
    const float* WO   = (const float*)d_in[11];
    float* out = (float*)d_out;

    float* base = nullptr;
    cudaGetSymbolAddress((void**)&base, g_scratch);

    __half* hb     = (__half*)base;
    __half* xhi    = hb;                __half* xlo    = xhi    + N_QKV;
    __half* WcThi  = xlo    + N_QKV;    __half* WcTlo  = WcThi  + N_WC;
    __half* WqThi  = WcTlo  + N_WC;     __half* WqTlo  = WqThi  + 3 * N_WX;
    __half* hhi    = WqTlo  + 3 * N_WX; __half* hlo    = hhi    + N_H;
    __half* QKVhi  = hlo    + N_H;      __half* QKVlo  = QKVhi  + 3 * N_QKV;
    __half* AOhi   = QKVlo  + 3 * N_QKV;__half* AOlo   = AOhi   + N_QKV;
    __half* WOhi   = AOlo   + N_QKV;    __half* WOlo   = WOhi   + N_WO;

    cudaFuncSetAttribute(hgemm<3, true>,
                         cudaFuncAttributeMaxDynamicSharedMemorySize, GEMM_SMEM);
    cudaFuncSetAttribute(hgemm<2, false>,
                         cudaFuncAttributeMaxDynamicSharedMemorySize, GEMM_SMEM);
    cudaFuncSetAttribute(hgemm64<3, true>,
                         cudaFuncAttributeMaxDynamicSharedMemorySize, GEMM64_SMEM);
    cudaFuncSetAttribute(flash_mma,
                         cudaFuncAttributeMaxDynamicSharedMemorySize, FLASH_SMEM);

    // 1) fused combines -> transposed fp16 hi/lo weights
    combine_compress_T<<<dim3(D / 32, B), 256>>>(cw, ci, cn, WcThi, WcTlo);
    combine_expand_T<<<dim3(D / 32, B, 3), 256>>>(wq, iq, wk, ik, wv, iv, pool,
                                                  WqThi, WqTlo);

    // 2) input splits
    split_kernel<<<(int)(N_QKV / 1024), 256>>>(x, xhi, xlo);
    split_kernel<<<(int)(N_WO  / 1024), 256>>>(WO, WOhi, WOlo);

    // 3) h = x @ WcT^T (3-product, 64-tile: 256 blocks fill the chip)
    hgemm64<3, true><<<dim3(R / 64, S / 64, B), 128, GEMM64_SMEM>>>(
        xhi, xlo, WcThi, WcTlo, nullptr, hhi, hlo,
        D, D, D, R, (long)S * D, (long)R * D, (long)S * R);

    // 4) fused QKV = h @ WqkvT^T (M=S, N=3D, K=R; one 1536-block launch)
    hgemm<3, true><<<dim3(3 * D / 128, S / 128, B), 256, GEMM_SMEM>>>(
        hhi, hlo, WqThi, WqTlo, nullptr, QKVhi, QKVlo,
        R, R, R, 3 * D, (long)S * R, (long)3 * D * R, (long)S * 3 * D);

    // 5) flash attention (reads fused QKV with stride 3D)
    flash_mma<<<dim3(S / 64, H, B), 128, FLASH_SMEM>>>(
        QKVhi, QKVlo, AOhi, AOlo);

    // 6) out = AO @ W_O^T (2-product)
    hgemm<2, false><<<dim3(D / 128, (B * S) / 128, 1), 256, GEMM_SMEM>>>(
        AOhi, AOlo, WOhi, WOlo, out, nullptr, nullptr,
        D, D, D, D, 0, 0, 0);
}

// round 15
// speedup vs baseline: 1.2566x; 1.2201x over previous
#include <cuda_runtime.h>
#include <cuda_fp16.h>
#include <cstdint>

// ---------------------------------------------------------------------------
// Problem constants
// ---------------------------------------------------------------------------
static constexpr int B   = 8;
static constexpr int S   = 1024;
static constexpr int D   = 1024;
static constexpr int H   = 16;
static constexpr int DH  = 64;
static constexpr int R   = 128;   // RANK
static constexpr int KC  = 16;
static constexpr int KE  = 8;

// ---------------------------------------------------------------------------
// Scratch layout (fp16 hi/lo pairs)
// ---------------------------------------------------------------------------
static constexpr size_t N_WC  = (size_t)B * D * R;
static constexpr size_t N_H   = (size_t)B * S * R;
static constexpr size_t N_WX  = (size_t)B * R * D;
static constexpr size_t N_QKV = (size_t)B * S * D;
static constexpr size_t N_WO  = (size_t)D * D;
static constexpr size_t HALVES =
    10 * N_QKV + 2 * N_WC + 6 * N_WX + 2 * N_H + 2 * N_WO;
static constexpr size_t SCRATCH_FLOATS = (HALVES + 1) / 2;

__device__ __align__(1024) float g_scratch[SCRATCH_FLOATS];

// ---------------------------------------------------------------------------
// Helpers
// ---------------------------------------------------------------------------
__device__ __forceinline__ void split2(float a, float b, uint32_t& hi, uint32_t& lo) {
    __half2 h = __floats2half2_rn(a, b);
    hi = *reinterpret_cast<uint32_t*>(&h);
    float2 f = __half22float2(h);
    __half2 l = __floats2half2_rn(a - f.x, b - f.y);
    lo = *reinterpret_cast<uint32_t*>(&l);
}
__device__ __forceinline__ uint32_t pack2(float a, float b) {
    __half2 h = __floats2half2_rn(a, b);
    return *reinterpret_cast<uint32_t*>(&h);
}

#define MMA_F16(ACC, A0, A1, A2, A3, B0, B1)                                   \
    asm volatile("mma.sync.aligned.m16n8k16.row.col.f32.f16.f16.f32 "          \
        "{%0,%1,%2,%3}, {%4,%5,%6,%7}, {%8,%9}, {%0,%1,%2,%3};"                \
        : "+f"((ACC)[0]), "+f"((ACC)[1]), "+f"((ACC)[2]), "+f"((ACC)[3])       \
        : "r"(A0), "r"(A1), "r"(A2), "r"(A3), "r"(B0), "r"(B1))

#define CP16(dst_half_ptr, src_ptr)                                            \
    asm volatile("cp.async.cg.shared.global [%0], [%1], 16;"                   \
        :: "r"((uint32_t)__cvta_generic_to_shared(dst_half_ptr)), "l"(src_ptr))

// ---------------------------------------------------------------------------
// Fused: compress combine -> transpose -> fp16 hi/lo split.
// ---------------------------------------------------------------------------
__global__ void combine_compress_T(const float* __restrict__ w,
                                   const int*   __restrict__ idx,
                                   const float* __restrict__ cn,
                                   __half* __restrict__ ohi,
                                   __half* __restrict__ olo)
{
    int dt = blockIdx.x * 32;
    int b  = blockIdx.y;
    __shared__ float s[32][129];
    __shared__ float sw[KC];
    __shared__ int   si[KC];
    int tid = threadIdx.x;
    if (tid < KC) { sw[tid] = w[b * KC + tid]; si[tid] = idx[b * KC + tid]; }
    __syncthreads();

    float a[16];
#pragma unroll
    for (int j = 0; j < 16; j++) a[j] = 0.f;
#pragma unroll
    for (int k = 0; k < KC; k++) {
        const float* src = cn + ((long)si[k] * D + dt) * R;
        float wk = sw[k];
#pragma unroll
        for (int j = 0; j < 16; j++)
            a[j] += wk * src[tid + j * 256];
    }
#pragma unroll
    for (int j = 0; j < 16; j++) {
        int i = tid + j * 256;
        s[i >> 7][i & 127] = a[j];
    }
    __syncthreads();

    int r = tid >> 1, dp = (tid & 1) * 16;
    uint32_t hb[8], lb[8];
#pragma unroll
    for (int p = 0; p < 8; p++)
        split2(s[dp + 2 * p][r], s[dp + 2 * p + 1][r], hb[p], lb[p]);
    long o = ((long)b * R + r) * D + dt + dp;
    ((uint4*)&ohi[o])[0] = ((uint4*)hb)[0];
    ((uint4*)&ohi[o])[1] = ((uint4*)hb)[1];
    ((uint4*)&olo[o])[0] = ((uint4*)lb)[0];
    ((uint4*)&olo[o])[1] = ((uint4*)lb)[1];
}

// ---------------------------------------------------------------------------
// Fused: expand combine -> transpose -> fp16 hi/lo split.
// Out layout for fused QKV gemm: W[(b*3+mat)*D + d][r].
// ---------------------------------------------------------------------------
__global__ void combine_expand_T(const float* __restrict__ wq, const int* __restrict__ iq,
                                 const float* __restrict__ wk, const int* __restrict__ ik,
                                 const float* __restrict__ wv, const int* __restrict__ iv,
                                 const float* __restrict__ pool,
                                 __half* __restrict__ Whi, __half* __restrict__ Wlo)
{
    int dt  = blockIdx.x * 32;
    int b   = blockIdx.y;
    int mat = blockIdx.z;
    const float* w  = (mat == 0) ? wq : (mat == 1) ? wk : wv;
    const int*   id = (mat == 0) ? iq : (mat == 1) ? ik : iv;

    __shared__ float s[32][129];
    __shared__ float sw[KE];
    __shared__ int   si[KE];
    int tid = threadIdx.x;
    if (tid < KE) { sw[tid] = w[b * KE + tid]; si[tid] = id[b * KE + tid]; }
    __syncthreads();

    float a[16];
#pragma unroll
    for (int j = 0; j < 16; j++) a[j] = 0.f;
#pragma unroll
    for (int k = 0; k < KE; k++) {
        const float* src = pool + (long)si[k] * R * D + dt;
        float wk_ = sw[k];
#pragma unroll
        for (int j = 0; j < 16; j++) {
            int i = tid + j * 256;
            a[j] += wk_ * src[(long)(i >> 5) * D + (i & 31)];
        }
    }
#pragma unroll
    for (int j = 0; j < 16; j++) {
        int i = tid + j * 256;
        s[i & 31][i >> 5] = a[j];
    }
    __syncthreads();

    int d = tid >> 3, rp = (tid & 7) * 16;
    uint32_t hb[8], lb[8];
#pragma unroll
    for (int p = 0; p < 8; p++)
        split2(s[d][rp + 2 * p], s[d][rp + 2 * p + 1], hb[p], lb[p]);
    long o = ((long)(b * 3 + mat) * D + dt + d) * R + rp;
    ((uint4*)&Whi[o])[0] = ((uint4*)hb)[0];
    ((uint4*)&Whi[o])[1] = ((uint4*)hb)[1];
    ((uint4*)&Wlo[o])[0] = ((uint4*)lb)[0];
    ((uint4*)&Wlo[o])[1] = ((uint4*)lb)[1];
}

// ---------------------------------------------------------------------------
// fp32 -> fp16 hi/lo elementwise
// ---------------------------------------------------------------------------
__global__ void split_kernel(const float* __restrict__ in,
                             __half* __restrict__ hi, __half* __restrict__ lo)
{
    long i = ((long)blockIdx.x * 256 + threadIdx.x) * 4;
    float4 v = *(const float4*)&in[i];
    uint32_t h0, l0, h1, l1;
    split2(v.x, v.y, h0, l0);
    split2(v.z, v.w, h1, l1);
    *(uint2*)&hi[i] = make_uint2(h0, h1);
    *(uint2*)&lo[i] = make_uint2(l0, l1);
}

// ---------------------------------------------------------------------------
// fp16-pair tensor-core GEMM, 128x128x32 tiles, 256 threads.
// NPROD=3: alo*bhi + ahi*blo + ahi*bhi (near-fp32)
// NPROD=2: alo*bhi + ahi*bhi          (B hi only)
// NPROD=1: ahi*bhi                    (pure fp16; only 2 tensors staged)
// ---------------------------------------------------------------------------
static constexpr int TILE_H    = 128 * 40;
static constexpr int GEMM_SMEM = 2 * 4 * TILE_H * 2;  // 81920 B

template <int NPROD, bool SPLIT_OUT>
__global__ void __launch_bounds__(256)
hgemm(const __half* __restrict__ Ahi, const __half* __restrict__ Alo,
      const __half* __restrict__ Bhi, const __half* __restrict__ Blo,
      float* __restrict__ C, __half* __restrict__ Chi, __half* __restrict__ Clo,
      int K, int lda, int ldb, int ldc, long sA, long sB, long sC)
{
    extern __shared__ __half sm[];
    int tid = threadIdx.x, wid = tid >> 5, lane = tid & 31;
    int wm = wid & 1, wn = wid >> 1;
    int qr = lane >> 2, qc = lane & 3;

    long zA = (long)blockIdx.z * sA, zB = (long)blockIdx.z * sB, zC = (long)blockIdx.z * sC;
    int m0 = blockIdx.y * 128, n0 = blockIdx.x * 128;

    const __half* srcs[4] = { Ahi + zA, Alo + zA, Bhi + zB, Blo + zB };
    int rbase[4] = { m0, m0, n0, n0 };
    int lds[4]   = { lda, lda, ldb, ldb };

    float acc[4][4][4];
#pragma unroll
    for (int mi = 0; mi < 4; mi++)
#pragma unroll
        for (int ni = 0; ni < 4; ni++)
#pragma unroll
            for (int c = 0; c < 4; c++) acc[mi][ni][c] = 0.f;

    int nt = K / 32;
    constexpr int NLOAD = (NPROD == 3) ? 8 : (NPROD == 2) ? 6 : 4;

    auto load_stage = [&](int kt, int st) {
        __half* sb = sm + st * 4 * TILE_H;
#pragma unroll
        for (int i = 0; i < NLOAD; i++) {
            int g = tid + i * 256;
            int tsr = g >> 9;
            int ti  = (NPROD == 1) ? tsr * 2 : tsr;   // 1P: {Ahi, Bhi}
            int rem = g & 511;
            int row = rem >> 2, ch = rem & 3;
            __half* dst = sb + ti * TILE_H + row * 40 + ch * 8;
            const __half* src = srcs[ti] + (long)(rbase[ti] + row) * lds[ti]
                                + kt * 32 + ch * 8;
            CP16(dst, src);
        }
        asm volatile("cp.async.commit_group;" ::: "memory");
    };

    load_stage(0, 0);

    for (int kt = 0; kt < nt; kt++) {
        if (kt + 1 < nt) {
            load_stage(kt + 1, (kt + 1) & 1);
            asm volatile("cp.async.wait_group 1;" ::: "memory");
        } else {
            asm volatile("cp.async.wait_group 0;" ::: "memory");
        }
        __syncthreads();

        const __half* sb = sm + (kt & 1) * 4 * TILE_H;
        const __half* As_hi = sb;
        const __half* As_lo = sb + TILE_H;
        const __half* Bs_hi = sb + 2 * TILE_H;
        const __half* Bs_lo = sb + 3 * TILE_H;

#pragma unroll
        for (int ks = 0; ks < 2; ks++) {
            uint32_t ahi[4][4], alo[4][4];
#pragma unroll
            for (int mi = 0; mi < 4; mi++) {
                int base = (wm * 64 + mi * 16 + qr) * 40 + ks * 16 + qc * 2;
                ahi[mi][0] = *(const uint32_t*)&As_hi[base];
                ahi[mi][1] = *(const uint32_t*)&As_hi[base + 8 * 40];
                ahi[mi][2] = *(const uint32_t*)&As_hi[base + 8];
                ahi[mi][3] = *(const uint32_t*)&As_hi[base + 8 * 40 + 8];
                if (NPROD >= 2) {
                    alo[mi][0] = *(const uint32_t*)&As_lo[base];
                    alo[mi][1] = *(const uint32_t*)&As_lo[base + 8 * 40];
                    alo[mi][2] = *(const uint32_t*)&As_lo[base + 8];
                    alo[mi][3] = *(const uint32_t*)&As_lo[base + 8 * 40 + 8];
                }
            }
            uint32_t bhi[4][2], blo[4][2];
#pragma unroll
            for (int ni = 0; ni < 4; ni++) {
                int base = (wn * 32 + ni * 8 + qr) * 40 + ks * 16 + qc * 2;
                bhi[ni][0] = *(const uint32_t*)&Bs_hi[base];
                bhi[ni][1] = *(const uint32_t*)&Bs_hi[base + 8];
                if (NPROD == 3) {
                    blo[ni][0] = *(const uint32_t*)&Bs_lo[base];
                    blo[ni][1] = *(const uint32_t*)&Bs_lo[base + 8];
                }
            }
#pragma unroll
            for (int mi = 0; mi < 4; mi++)
#pragma unroll
                for (int ni = 0; ni < 4; ni++) {
                    if (NPROD >= 2)
                        MMA_F16(acc[mi][ni], alo[mi][0], alo[mi][1], alo[mi][2], alo[mi][3],
                                bhi[ni][0], bhi[ni][1]);
                    if (NPROD == 3)
                        MMA_F16(acc[mi][ni], ahi[mi][0], ahi[mi][1], ahi[mi][2], ahi[mi][3],
                                blo[ni][0], blo[ni][1]);
                    MMA_F16(acc[mi][ni], ahi[mi][0], ahi[mi][1], ahi[mi][2], ahi[mi][3],
                            bhi[ni][0], bhi[ni][1]);
                }
        }
        __syncthreads();
    }

#pragma unroll
    for (int mi = 0; mi < 4; mi++) {
        int row = m0 + wm * 64 + mi * 16 + qr;
#pragma unroll
        for (int ni = 0; ni < 4; ni++) {
            int col = n0 + wn * 32 + ni * 8 + qc * 2;
            if (SPLIT_OUT) {
                uint32_t h, l;
                split2(acc[mi][ni][0], acc[mi][ni][1], h, l);
                *(uint32_t*)&Chi[zC + (long)row * ldc + col] = h;
                *(uint32_t*)&Clo[zC + (long)row * ldc + col] = l;
                split2(acc[mi][ni][2], acc[mi][ni][3], h, l);
                *(uint32_t*)&Chi[zC + (long)(row + 8) * ldc + col] = h;
                *(uint32_t*)&Clo[zC + (long)(row + 8) * ldc + col] = l;
            } else {
                *(float2*)&C[zC + (long)row * ldc + col] =
                    make_float2(acc[mi][ni][0], acc[mi][ni][1]);
                *(float2*)&C[zC + (long)(row + 8) * ldc + col] =
                    make_float2(acc[mi][ni][2], acc[mi][ni][3]);
            }
        }
    }
}

// ---------------------------------------------------------------------------
// 64x64x32-tile variant (128 threads) for the small h GEMM.
// ---------------------------------------------------------------------------
static constexpr int TILE64_H    = 64 * 40;
static constexpr int GEMM64_SMEM = 2 * 4 * TILE64_H * 2;  // 40960 B

template <int NPROD, bool SPLIT_OUT>
__global__ void __launch_bounds__(128)
hgemm64(const __half* __restrict__ Ahi, const __half* __restrict__ Alo,
        const __half* __restrict__ Bhi, const __half* __restrict__ Blo,
        float* __restrict__ C, __half* __restrict__ Chi, __half* __restrict__ Clo,
        int K, int lda, int ldb, int ldc, long sA, long sB, long sC)
{
    extern __shared__ __half sm[];
    int tid = threadIdx.x, wid = tid >> 5, lane = tid & 31;
    int wm = wid & 1, wn = wid >> 1;
    int qr = lane >> 2, qc = lane & 3;

    long zA = (long)blockIdx.z * sA, zB = (long)blockIdx.z * sB, zC = (long)blockIdx.z * sC;
    int m0 = blockIdx.y * 64, n0 = blockIdx.x * 64;

    const __half* srcs[4] = { Ahi + zA, Alo + zA, Bhi + zB, Blo + zB };
    int rbase[4] = { m0, m0, n0, n0 };
    int lds[4]   = { lda, lda, ldb, ldb };

    float acc[2][4][4];
#pragma unroll
    for (int mi = 0; mi < 2; mi++)
#pragma unroll
        for (int ni = 0; ni < 4; ni++)
#pragma unroll
            for (int c = 0; c < 4; c++) acc[mi][ni][c] = 0.f;

    int nt = K / 32;
    constexpr int NLOAD = (NPROD == 3) ? 8 : (NPROD == 2) ? 6 : 4;

    auto load_stage = [&](int kt, int st) {
        __half* sb = sm + st * 4 * TILE64_H;
#pragma unroll
        for (int i = 0; i < NLOAD; i++) {
            int g = tid + i * 128;
            int tsr = g >> 8;
            int ti  = (NPROD == 1) ? tsr * 2 : tsr;
            int rem = g & 255;
            int row = rem >> 2, ch = rem & 3;
            __half* dst = sb + ti * TILE64_H + row * 40 + ch * 8;
            const __half* src = srcs[ti] + (long)(rbase[ti] + row) * lds[ti]
                                + kt * 32 + ch * 8;
            CP16(dst, src);
        }
        asm volatile("cp.async.commit_group;" ::: "memory");
    };

    load_stage(0, 0);

    for (int kt = 0; kt < nt; kt++) {
        if (kt + 1 < nt) {
            load_stage(kt + 1, (kt + 1) & 1);
            asm volatile("cp.async.wait_group 1;" ::: "memory");
        } else {
            asm volatile("cp.async.wait_group 0;" ::: "memory");
        }
        __syncthreads();

        const __half* sb = sm + (kt & 1) * 4 * TILE64_H;
        const __half* As_hi = sb;
        const __half* As_lo = sb + TILE64_H;
        const __half* Bs_hi = sb + 2 * TILE64_H;
        const __half* Bs_lo = sb + 3 * TILE64_H;

#pragma unroll
        for (int ks = 0; ks < 2; ks++) {
            uint32_t ahi[2][4], alo[2][4];
#pragma unroll
            for (int mi = 0; mi < 2; mi++) {
                int base = (wm * 32 + mi * 16 + qr) * 40 + ks * 16 + qc * 2;
                ahi[mi][0] = *(const uint32_t*)&As_hi[base];
                ahi[mi][1] = *(const uint32_t*)&As_hi[base + 8 * 40];
                ahi[mi][2] = *(const uint32_t*)&As_hi[base + 8];
                ahi[mi][3] = *(const uint32_t*)&As_hi[base + 8 * 40 + 8];
                if (NPROD >= 2) {
                    alo[mi][0] = *(const uint32_t*)&As_lo[base];
                    alo[mi][1] = *(const uint32_t*)&As_lo[base + 8 * 40];
                    alo[mi][2] = *(const uint32_t*)&As_lo[base + 8];
                    alo[mi][3] = *(const uint32_t*)&As_lo[base + 8 * 40 + 8];
                }
            }
            uint32_t bhi[4][2], blo[4][2];
#pragma unroll
            for (int ni = 0; ni < 4; ni++) {
                int base = (wn * 32 + ni * 8 + qr) * 40 + ks * 16 + qc * 2;
                bhi[ni][0] = *(const uint32_t*)&Bs_hi[base];
                bhi[ni][1] = *(const uint32_t*)&Bs_hi[base + 8];
                if (NPROD == 3) {
                    blo[ni][0] = *(const uint32_t*)&Bs_lo[base];
                    blo[ni][1] = *(const uint32_t*)&Bs_lo[base + 8];
                }
            }
#pragma unroll
            for (int mi = 0; mi < 2; mi++)
#pragma unroll
                for (int ni = 0; ni < 4; ni++) {
                    if (NPROD >= 2)
                        MMA_F16(acc[mi][ni], alo[mi][0], alo[mi][1], alo[mi][2], alo[mi][3],
                                bhi[ni][0], bhi[ni][1]);
                    if (NPROD == 3)
                        MMA_F16(acc[mi][ni], ahi[mi][0], ahi[mi][1], ahi[mi][2], ahi[mi][3],
                                blo[ni][0], blo[ni][1]);
                    MMA_F16(acc[mi][ni], ahi[mi][0], ahi[mi][1], ahi[mi][2], ahi[mi][3],
                            bhi[ni][0], bhi[ni][1]);
                }
        }
        __syncthreads();
    }

#pragma unroll
    for (int mi = 0; mi < 2; mi++) {
        int row = m0 + wm * 32 + mi * 16 + qr;
#pragma unroll
        for (int ni = 0; ni < 4; ni++) {
            int col = n0 + wn * 32 + ni * 8 + qc * 2;
            if (SPLIT_OUT) {
                uint32_t h, l;
                split2(acc[mi][ni][0], acc[mi][ni][1], h, l);
                *(uint32_t*)&Chi[zC + (long)row * ldc + col] = h;
                *(uint32_t*)&Clo[zC + (long)row * ldc + col] = l;
                split2(acc[mi][ni][2], acc[mi][ni][3], h, l);
                *(uint32_t*)&Chi[zC + (long)(row + 8) * ldc + col] = h;
                *(uint32_t*)&Clo[zC + (long)(row + 8) * ldc + col] = l;
            } else {
                *(float2*)&C[zC + (long)row * ldc + col] =
                    make_float2(acc[mi][ni][0], acc[mi][ni][1]);
                *(float2*)&C[zC + (long)(row + 8) * ldc + col] =
                    make_float2(acc[mi][ni][2], acc[mi][ni][3]);
            }
        }
    }
}

// ---------------------------------------------------------------------------
// Tensor-core causal flash attention. QK 3-product; PV 1-product (P_hi x V_hi).
// AO written as fp16 hi ONLY (WO gemm is 1-product).
// ---------------------------------------------------------------------------
static constexpr int LDQKV = 3 * D;
static constexpr int FA_QHI = 0, FA_QLO = 4608, FA_KHI = 9216, FA_KLO = 13824,
                     FA_VHI = 18432, FA_HALVES = 22528;
static constexpr int FLASH_SMEM = FA_HALVES * 2;   // 45056 B

__global__ void __launch_bounds__(128)
flash_mma(const __half* __restrict__ QKVhi, const __half* __restrict__ QKVlo,
          __half* __restrict__ AOhi)
{
    extern __shared__ __half sm[];
    int qt = blockIdx.x, h = blockIdx.y, b = blockIdx.z;
    int q0 = qt * 64;
    int tid = threadIdx.x, w = tid >> 5, lane = tid & 31;
    int qr = lane >> 2, qc = lane & 3;
    int rb = w * 16;

    const long bQKV = (long)b * S * LDQKV;
    const __half* Qh = QKVhi + bQKV + (long)q0 * LDQKV + h * 64;
    const __half* Ql = QKVlo + bQKV + (long)q0 * LDQKV + h * 64;
    const __half* Kh = QKVhi + bQKV + D + h * 64;
    const __half* Kl = QKVlo + bQKV + D + h * 64;
    const __half* Vh = QKVhi + bQKV + 2 * D + h * 64;

    auto load_q = [&]() {
#pragma unroll
        for (int i = 0; i < 8; i++) {
            int g = tid + i * 128;
            int tsr = g >> 9, rem = g & 511;
            int row = rem >> 3, ch = rem & 7;
            __half* dst = sm + (tsr ? FA_QLO : FA_QHI) + row * 72 + ch * 8;
            const __half* src = (tsr ? Ql : Qh) + (long)row * LDQKV + ch * 8;
            CP16(dst, src);
        }
    };
    auto load_k = [&](int kt) {
#pragma unroll
        for (int i = 0; i < 8; i++) {
            int g = tid + i * 128;
            int tsr = g >> 9, rem = g & 511;
            int row = rem >> 3, ch = rem & 7;
            __half* dst = sm + (tsr ? FA_KLO : FA_KHI) + row * 72 + ch * 8;
            const __half* src = (tsr ? Kl : Kh) + (long)(kt * 64 + row) * LDQKV + ch * 8;
            CP16(dst, src);
        }
        asm volatile("cp.async.commit_group;" ::: "memory");
    };
    auto load_v = [&](int kt) {
#pragma unroll
        for (int i = 0; i < 4; i++) {
            int g = tid + i * 128;
            int row = g >> 3, ch = g & 7;
            int col = (ch * 8) ^ ((row & 7) << 3);
            __half* dst = sm + FA_VHI + row * 64 + col;
            const __half* src = Vh + (long)(kt * 64 + row) * LDQKV + ch * 8;
            CP16(dst, src);
        }
        asm volatile("cp.async.commit_group;" ::: "memory");
    };

    load_q();
    load_k(0);
    load_v(0);
    asm volatile("cp.async.wait_group 0;" ::: "memory");
    __syncthreads();

    uint32_t qa_hi[4][4], qa_lo[4][4];
#pragma unroll
    for (int j = 0; j < 4; j++) {
        int base0 = (rb + qr) * 72 + j * 16 + qc * 2;
#pragma unroll
        for (int r = 0; r < 4; r++) {
            int off = base0 + (r & 1) * 8 * 72 + (r >> 1) * 8;
            qa_hi[j][r] = *(const uint32_t*)&sm[FA_QHI + off];
            qa_lo[j][r] = *(const uint32_t*)&sm[FA_QLO + off];
        }
    }

    float o[8][4];
#pragma unroll
    for (int n = 0; n < 8; n++)
#pragma unroll
        for (int c = 0; c < 4; c++) o[n][c] = 0.f;
    float m0 = -1e30f, m1 = -1e30f, l0 = 0.f, l1 = 0.f;

    const float scale = 0.125f;
    int row0 = q0 + rb + qr, row1 = row0 + 8;
    int nkt = qt + 1;

    for (int kt = 0; kt < nkt; kt++) {
        float s[8][4];
#pragma unroll
        for (int n = 0; n < 8; n++)
#pragma unroll
            for (int c = 0; c < 4; c++) s[n][c] = 0.f;

#pragma unroll
        for (int n = 0; n < 8; n++) {
#pragma unroll
            for (int j = 0; j < 4; j++) {
                int base = (n * 8 + qr) * 72 + j * 16 + qc * 2;
                uint32_t bh0 = *(const uint32_t*)&sm[FA_KHI + base];
                uint32_t bh1 = *(const uint32_t*)&sm[FA_KHI + base + 8];
                uint32_t bl0 = *(const uint32_t*)&sm[FA_KLO + base];
                uint32_t bl1 = *(const uint32_t*)&sm[FA_KLO + base + 8];
                MMA_F16(s[n], qa_lo[j][0], qa_lo[j][1], qa_lo[j][2], qa_lo[j][3], bh0, bh1);
                MMA_F16(s[n], qa_hi[j][0], qa_hi[j][1], qa_hi[j][2], qa_hi[j][3], bl0, bl1);
                MMA_F16(s[n], qa_hi[j][0], qa_hi[j][1], qa_hi[j][2], qa_hi[j][3], bh0, bh1);
            }
        }

        __syncthreads();
        bool more = (kt + 1 < nkt);
        if (more) load_k(kt + 1);

        float tm0 = -1e30f, tm1 = -1e30f;
#pragma unroll
        for (int n = 0; n < 8; n++) {
            int cb = kt * 64 + n * 8 + qc * 2;
            s[n][0] = (cb     > row0) ? -1e30f : s[n][0] * scale;
            s[n][1] = (cb + 1 > row0) ? -1e30f : s[n][1] * scale;
            s[n][2] = (cb     > row1) ? -1e30f : s[n][2] * scale;
            s[n][3] = (cb + 1 > row1) ? -1e30f : s[n][3] * scale;
            tm0 = fmaxf(tm0, fmaxf(s[n][0], s[n][1]));
            tm1 = fmaxf(tm1, fmaxf(s[n][2], s[n][3]));
        }
        tm0 = fmaxf(tm0, __shfl_xor_sync(0xffffffffu, tm0, 1));
        tm0 = fmaxf(tm0, __shfl_xor_sync(0xffffffffu, tm0, 2));
        tm1 = fmaxf(tm1, __shfl_xor_sync(0xffffffffu, tm1, 1));
        tm1 = fmaxf(tm1, __shfl_xor_sync(0xffffffffu, tm1, 2));

        float mn0 = fmaxf(m0, tm0), mn1 = fmaxf(m1, tm1);
        float al0 = __expf(m0 - mn0), al1 = __expf(m1 - mn1);
        m0 = mn0; m1 = mn1;

        float rs0 = 0.f, rs1 = 0.f;
#pragma unroll
        for (int n = 0; n < 8; n++) {
            s[n][0] = __expf(s[n][0] - mn0);
            s[n][1] = __expf(s[n][1] - mn0);
            s[n][2] = __expf(s[n][2] - mn1);
            s[n][3] = __expf(s[n][3] - mn1);
            rs0 += s[n][0] + s[n][1];
            rs1 += s[n][2] + s[n][3];
        }
        rs0 += __shfl_xor_sync(0xffffffffu, rs0, 1);
        rs0 += __shfl_xor_sync(0xffffffffu, rs0, 2);
        rs1 += __shfl_xor_sync(0xffffffffu, rs1, 1);
        rs1 += __shfl_xor_sync(0xffffffffu, rs1, 2);
        l0 = l0 * al0 + rs0;
        l1 = l1 * al1 + rs1;
#pragma unroll
        for (int n = 0; n < 8; n++) {
            o[n][0] *= al0; o[n][1] *= al0;
            o[n][2] *= al1; o[n][3] *= al1;
        }

        // ---- O += P_hi V_hi (1-product) ----
#pragma unroll
        for (int j = 0; j < 4; j++) {
            uint32_t phi[4];
            phi[0] = pack2(s[2 * j][0],     s[2 * j][1]);
            phi[1] = pack2(s[2 * j][2],     s[2 * j][3]);
            phi[2] = pack2(s[2 * j + 1][0], s[2 * j + 1][1]);
            phi[3] = pack2(s[2 * j + 1][2], s[2 * j + 1][3]);
            int kr = j * 16 + (lane & 15);
#pragma unroll
            for (int np = 0; np < 4; np++) {
                int nb = np * 16 + (lane >> 4) * 8;
                uint32_t addr_h = (uint32_t)__cvta_generic_to_shared(
                    &sm[FA_VHI + kr * 64 + (nb ^ ((kr & 7) << 3))]);
                uint32_t vh[4];
                asm volatile("ldmatrix.sync.aligned.m8n8.x4.trans.shared.b16 "
                             "{%0,%1,%2,%3}, [%4];"
                             : "=r"(vh[0]), "=r"(vh[1]), "=r"(vh[2]), "=r"(vh[3])
                             : "r"(addr_h));
                MMA_F16(o[np * 2],     phi[0], phi[1], phi[2], phi[3], vh[0], vh[1]);
                MMA_F16(o[np * 2 + 1], phi[0], phi[1], phi[2], phi[3], vh[2], vh[3]);
            }
        }

        __syncthreads();
        if (more) {
            load_v(kt + 1);
            asm volatile("cp.async.wait_group 0;" ::: "memory");
            __syncthreads();
        }
    }

    float inv0 = 1.0f / l0, inv1 = 1.0f / l1;
    long obase = (long)b * S * D + (long)h * 64;
#pragma unroll
    for (int n = 0; n < 8; n++) {
        int col = n * 8 + qc * 2;
        *(uint32_t*)&AOhi[obase + (long)row0 * D + col] =
            pack2(o[n][0] * inv0, o[n][1] * inv0);
        *(uint32_t*)&AOhi[obase + (long)row1 * D + col] =
            pack2(o[n][2] * inv1, o[n][3] * inv1);
    }
}

// ---------------------------------------------------------------------------
// Host entry
// ---------------------------------------------------------------------------
extern "C" void kernel_launch(void* const* d_in, const int* in_sizes, int n_in,
                              void* d_out, int out_size)
{
    const float* x    = (const float*)d_in[0];
    const float* cw   = (const float*)d_in[1];
    const int*   ci   = (const int*)  d_in[2];
    const float* wq   = (const float*)d_in[3];
    const int*   iq   = (const int*)  d_in[4];
    const float* wk   = (const float*)d_in[5];
    const int*   ik   = (const int*)  d_in[6];
    const float* wv   = (const float*)d_in[7];
    const int*   iv   = (const int*)  d_in[8];
    const float* cn   = (const float*)d_in[9];
    const float* pool = (const float*)d_in[10];
    const float* WO   = (const float*)d_in[11];
    float* out = (float*)d_out;

    float* base = nullptr;
    cudaGetSymbolAddress((void**)&base, g_scratch);

    __half* hb     = (__half*)base;
    __half* xhi    = hb;                __half* xlo    = xhi    + N_QKV;
    __half* WcThi  = xlo    + N_QKV;    __half* WcTlo  = WcThi  + N_WC;
    __half* WqThi  = WcTlo  + N_WC;     __half* WqTlo  = WqThi  + 3 * N_WX;
    __half* hhi    = WqTlo  + 3 * N_WX; __half* hlo    = hhi    + N_H;
    __half* QKVhi  = hlo    + N_H;      __half* QKVlo  = QKVhi  + 3 * N_QKV;
    __half* AOhi   = QKVlo  + 3 * N_QKV;
    __half* WOhi   = AOhi   + 2 * N_QKV;
    __half* WOlo   = WOhi   + N_WO;

    cudaFuncSetAttribute(hgemm<3, true>,
                         cudaFuncAttributeMaxDynamicSharedMemorySize, GEMM_SMEM);
    cudaFuncSetAttribute(hgemm<1, false>,
                         cudaFuncAttributeMaxDynamicSharedMemorySize, GEMM_SMEM);
    cudaFuncSetAttribute(hgemm64<3, true>,
                         cudaFuncAttributeMaxDynamicSharedMemorySize, GEMM64_SMEM);
    cudaFuncSetAttribute(flash_mma,
                         cudaFuncAttributeMaxDynamicSharedMemorySize, FLASH_SMEM);

    // 1) fused combines -> transposed fp16 hi/lo weights
    combine_compress_T<<<dim3(D / 32, B), 256>>>(cw, ci, cn, WcThi, WcTlo);
    combine_expand_T<<<dim3(D / 32, B, 3), 256>>>(wq, iq, wk, ik, wv, iv, pool,
                                                  WqThi, WqTlo);

    // 2) input splits (WO lo written but unused by 1-product gemm)
    split_kernel<<<(int)(N_QKV / 1024), 256>>>(x, xhi, xlo);
    split_kernel<<<(int)(N_WO  / 1024), 256>>>(WO, WOhi, WOlo);

    // 3) h = x @ WcT^T (3-product, 64-tile fills the chip)
    hgemm64<3, true><<<dim3(R / 64, S / 64, B), 128, GEMM64_SMEM>>>(
        xhi, xlo, WcThi, WcTlo, nullptr, hhi, hlo,
        D, D, D, R, (long)S * D, (long)R * D, (long)S * R);

    // 4) fused QKV = h @ WqkvT^T (M=S, N=3D, K=R; 3-product)
    hgemm<3, true><<<dim3(3 * D / 128, S / 128, B), 256, GEMM_SMEM>>>(
        hhi, hlo, WqThi, WqTlo, nullptr, QKVhi, QKVlo,
        R, R, R, 3 * D, (long)S * R, (long)3 * D * R, (long)S * 3 * D);

    // 5) flash attention (QK 3-product, PV 1-product; AO hi only)
    flash_mma<<<dim3(S / 64, H, B), 128, FLASH_SMEM>>>(
        QKVhi, QKVlo, AOhi);

    // 6) out = AO @ W_O^T (1-product fp16)
    hgemm<1, false><<<dim3(D / 128, (B * S) / 128, 1), 256, GEMM_SMEM>>>(
        AOhi, AOhi, WOhi, WOhi, out, nullptr, nullptr,
        D, D, D, D, 0, 0, 0);
}